// round 4
// baseline (speedup 1.0000x reference)
#include <cuda_runtime.h>
#include <cstdint>

// ---------------- problem constants ----------------
#define BATCH   16
#define SEQ     4096
#define CDIM    1024
#define NHEAD   16
#define DHEAD   64
#define LTOK    77
#define CENC    768
#define MQ      (BATCH*SEQ)      // 65536
#define MKV     (BATCH*LTOK)     // 1232

// ---------------- scratch ----------------
__device__ float g_q[(size_t)MQ * CDIM];
__device__ float g_attn[(size_t)MQ * CDIM];
__device__ float g_k[(size_t)MKV * CDIM];
__device__ float g_v[(size_t)MKV * CDIM];

__device__ __forceinline__ unsigned f2tf32(float x) {
    unsigned r;
    asm("cvt.rna.tf32.f32 %0, %1;" : "=r"(r) : "f"(x));
    return r;
}

// ============================================================
// TF32 tensor-core GEMM (legacy mma path — proven at ~122 TF/s):
// C[M,N] = A[M,K] @ B[K,N] (+bias). Block 128x128x16, 256 thr.
// ============================================================
#define PA 136
#define PB 136

__global__ void __launch_bounds__(256, 2) gemm_tf32(
    const float* __restrict__ A, const float* __restrict__ B,
    float* __restrict__ C, int M, int K, int N,
    const float* __restrict__ bias)
{
    __shared__ unsigned As[16 * PA];
    __shared__ unsigned Bs[16 * PB];

    const int t    = threadIdx.x;
    const int m0   = blockIdx.y * 128;
    const int n0   = blockIdx.x * 128;
    const int lane = t & 31;
    const int wid  = t >> 5;
    const int wm   = (wid >> 2) * 64;
    const int wn   = (wid & 3) * 32;
    const int gid  = lane >> 2;
    const int tg   = lane & 3;

    float acc[4][4][4];
#pragma unroll
    for (int i = 0; i < 4; i++)
#pragma unroll
        for (int j = 0; j < 4; j++)
#pragma unroll
            for (int r = 0; r < 4; r++) acc[i][j][r] = 0.f;

    for (int kt = 0; kt < K; kt += 16) {
#pragma unroll
        for (int i = 0; i < 2; i++) {
            int f  = t + i * 256;
            int m  = f >> 2;
            int kq = (f & 3) << 2;
            float4 val = make_float4(0.f, 0.f, 0.f, 0.f);
            int grow = m0 + m;
            if (grow < M)
                val = *(const float4*)(A + (size_t)grow * K + kt + kq);
            As[(kq + 0) * PA + m] = f2tf32(val.x);
            As[(kq + 1) * PA + m] = f2tf32(val.y);
            As[(kq + 2) * PA + m] = f2tf32(val.z);
            As[(kq + 3) * PA + m] = f2tf32(val.w);
        }
#pragma unroll
        for (int i = 0; i < 2; i++) {
            int f  = t + i * 256;
            int kr = f >> 5;
            int nq = (f & 31) << 2;
            float4 val = *(const float4*)(B + (size_t)(kt + kr) * N + n0 + nq);
            uint4 w;
            w.x = f2tf32(val.x); w.y = f2tf32(val.y);
            w.z = f2tf32(val.z); w.w = f2tf32(val.w);
            *(uint4*)(&Bs[kr * PB + nq]) = w;
        }
        __syncthreads();

#pragma unroll
        for (int kk = 0; kk < 16; kk += 8) {
            unsigned a[4][4], bf[4][2];
#pragma unroll
            for (int mf = 0; mf < 4; mf++) {
                int mb = wm + mf * 16 + gid;
                a[mf][0] = As[(kk + tg) * PA + mb];
                a[mf][1] = As[(kk + tg) * PA + mb + 8];
                a[mf][2] = As[(kk + tg + 4) * PA + mb];
                a[mf][3] = As[(kk + tg + 4) * PA + mb + 8];
            }
#pragma unroll
            for (int nf = 0; nf < 4; nf++) {
                int nb = wn + nf * 8 + gid;
                bf[nf][0] = Bs[(kk + tg) * PB + nb];
                bf[nf][1] = Bs[(kk + tg + 4) * PB + nb];
            }
#pragma unroll
            for (int mf = 0; mf < 4; mf++)
#pragma unroll
                for (int nf = 0; nf < 4; nf++)
                    asm volatile(
                        "mma.sync.aligned.m16n8k8.row.col.f32.tf32.tf32.f32 "
                        "{%0,%1,%2,%3}, {%4,%5,%6,%7}, {%8,%9}, {%0,%1,%2,%3};"
                        : "+f"(acc[mf][nf][0]), "+f"(acc[mf][nf][1]),
                          "+f"(acc[mf][nf][2]), "+f"(acc[mf][nf][3])
                        : "r"(a[mf][0]), "r"(a[mf][1]),
                          "r"(a[mf][2]), "r"(a[mf][3]),
                          "r"(bf[nf][0]), "r"(bf[nf][1]));
        }
        __syncthreads();
    }

#pragma unroll
    for (int mf = 0; mf < 4; mf++) {
#pragma unroll
        for (int nf = 0; nf < 4; nf++) {
            int row = m0 + wm + mf * 16 + gid;
            int col = n0 + wn + nf * 8 + tg * 2;
            float b0 = 0.f, b1 = 0.f;
            if (bias) { b0 = bias[col]; b1 = bias[col + 1]; }
            if (row < M) {
                float2 r0 = make_float2(acc[mf][nf][0] + b0, acc[mf][nf][1] + b1);
                *(float2*)(C + (size_t)row * N + col) = r0;
            }
            if (row + 8 < M) {
                float2 r1 = make_float2(acc[mf][nf][2] + b0, acc[mf][nf][3] + b1);
                *(float2*)(C + (size_t)(row + 8) * N + col) = r1;
            }
        }
    }
}

// ============================================================
// Fused cross-attention, register-resident Q:
// stage Q tile in smem (coalesced gmem load), copy each thread's
// row to 64 registers ONCE, then run all 77 kv-iterations from
// registers. K/V smem reads are warp-broadcast (conflict-free).
// ============================================================
#define TILE_S 256
#define KV_F4  (LTOK * (DHEAD / 4))
#define ATTN_SMEM ((2 * LTOK * DHEAD + TILE_S * DHEAD) * (int)sizeof(float))

__global__ void __launch_bounds__(TILE_S) attn_kernel(
    const float* __restrict__ q, const float* __restrict__ k,
    const float* __restrict__ v, float* __restrict__ o)
{
    extern __shared__ float sm[];
    float* Ks = sm;                        // 77*64
    float* Vs = Ks + LTOK * DHEAD;         // 77*64
    float* Qs = Vs + LTOK * DHEAD;         // 256*64, xor-swizzled float4

    const int bh = blockIdx.y;
    const int b  = bh >> 4;
    const int h  = bh & 15;
    const int s0 = blockIdx.x * TILE_S;
    const int t  = threadIdx.x;

    // stage K, V (coalesced)
    const float* kbase = k + (size_t)(b * LTOK) * CDIM + h * DHEAD;
    const float* vbase = v + (size_t)(b * LTOK) * CDIM + h * DHEAD;
    for (int i = t; i < KV_F4; i += TILE_S) {
        int j = i >> 4, c = i & 15;
        ((float4*)Ks)[j * 16 + c] = *(const float4*)(kbase + (size_t)j * CDIM + c * 4);
        ((float4*)Vs)[j * 16 + c] = *(const float4*)(vbase + (size_t)j * CDIM + c * 4);
    }
    // stage Q (coalesced), swizzled so the reg-fill below is conflict-free
    const float* qbase = q + (size_t)(b * SEQ + s0) * CDIM + h * DHEAD;
    for (int f = t; f < TILE_S * 16; f += TILE_S) {
        int r = f >> 4, c = f & 15;
        float4 val = *(const float4*)(qbase + (size_t)r * CDIM + c * 4);
        ((float4*)Qs)[r * 16 + (c ^ (r & 7))] = val;
    }
    __syncthreads();

    // copy this thread's Q row to registers (one-time cost)
    const int row = t;
    const int sw  = row & 7;
    float4 qr[16];
#pragma unroll
    for (int c = 0; c < 16; c++)
        qr[c] = ((const float4*)Qs)[row * 16 + (c ^ sw)];

    float accum[DHEAD];
#pragma unroll
    for (int d = 0; d < DHEAD; d++) accum[d] = 0.f;
    float lsum = 0.f;
    const float scale = 0.125f;  // 1/sqrt(64)

    for (int j = 0; j < LTOK; j++) {
        float s = 0.f;
#pragma unroll
        for (int c = 0; c < 16; c++) {
            float4 kv = ((const float4*)Ks)[j * 16 + c];  // broadcast
            s += qr[c].x * kv.x + qr[c].y * kv.y + qr[c].z * kv.z + qr[c].w * kv.w;
        }
        float e = __expf(s * scale);
        lsum += e;
#pragma unroll
        for (int c = 0; c < 16; c++) {
            float4 vv = ((const float4*)Vs)[j * 16 + c];  // broadcast
            accum[c * 4 + 0] += e * vv.x;
            accum[c * 4 + 1] += e * vv.y;
            accum[c * 4 + 2] += e * vv.z;
            accum[c * 4 + 3] += e * vv.w;
        }
    }

    const float inv = 1.0f / lsum;
    float* obase = o + (size_t)(b * SEQ + s0 + row) * CDIM + h * DHEAD;
#pragma unroll
    for (int c = 0; c < 16; c++) {
        float4 r = make_float4(accum[c * 4 + 0] * inv, accum[c * 4 + 1] * inv,
                               accum[c * 4 + 2] * inv, accum[c * 4 + 3] * inv);
        ((float4*)obase)[c] = r;
    }
}

// ============================================================
// launch
// ============================================================
extern "C" void kernel_launch(void* const* d_in, const int* in_sizes, int n_in,
                              void* d_out, int out_size)
{
    const float* hs  = (const float*)d_in[0];
    const float* enc = (const float*)d_in[1];
    const float* Wq  = (const float*)d_in[2];
    const float* Wk  = (const float*)d_in[3];
    const float* Wv  = (const float*)d_in[4];
    const float* Wo  = (const float*)d_in[5];
    const float* bo  = (const float*)d_in[6];
    float* out = (float*)d_out;
    (void)in_sizes; (void)n_in; (void)out_size;

    float *qb, *kb, *vb, *ab;
    cudaGetSymbolAddress((void**)&qb, g_q);
    cudaGetSymbolAddress((void**)&kb, g_k);
    cudaGetSymbolAddress((void**)&vb, g_v);
    cudaGetSymbolAddress((void**)&ab, g_attn);

    dim3 blk(256);

    // q = hs @ Wq
    gemm_tf32<<<dim3(CDIM / 128, MQ / 128), blk>>>(hs, Wq, qb, MQ, CDIM, CDIM, nullptr);
    // k = enc @ Wk, v = enc @ Wv
    gemm_tf32<<<dim3(CDIM / 128, (MKV + 127) / 128), blk>>>(enc, Wk, kb, MKV, CENC, CDIM, nullptr);
    gemm_tf32<<<dim3(CDIM / 128, (MKV + 127) / 128), blk>>>(enc, Wv, vb, MKV, CENC, CDIM, nullptr);

    // fused attention (register-resident Q)
    cudaFuncSetAttribute(attn_kernel, cudaFuncAttributeMaxDynamicSharedMemorySize, ATTN_SMEM);
    attn_kernel<<<dim3(SEQ / TILE_S, BATCH * NHEAD), TILE_S, ATTN_SMEM>>>(qb, kb, vb, ab);

    // out = attn @ Wo + bo
    gemm_tf32<<<dim3(CDIM / 128, MQ / 128), blk>>>(ab, Wo, out, MQ, CDIM, CDIM, bo);
}

// round 5
// speedup vs baseline: 1.0611x; 1.0611x over previous
#include <cuda_runtime.h>
#include <cstdint>

// ---------------- problem constants ----------------
#define BATCH   16
#define SEQ     4096
#define CDIM    1024
#define NHEAD   16
#define DHEAD   64
#define LTOK    77
#define CENC    768
#define MQ      (BATCH*SEQ)      // 65536
#define MKV     (BATCH*LTOK)     // 1232

// ---------------- scratch ----------------
__device__ float g_q[(size_t)MQ * CDIM];
__device__ float g_attn[(size_t)MQ * CDIM];
__device__ float g_k[(size_t)MKV * CDIM];
__device__ float g_v[(size_t)MKV * CDIM];

__device__ __forceinline__ unsigned f2tf32(float x) {
    unsigned r;
    asm("cvt.rna.tf32.f32 %0, %1;" : "=r"(r) : "f"(x));
    return r;
}

// ============================================================
// TF32 tensor-core GEMM core (legacy mma, ~122 TF/s proven).
// ============================================================
#define PA 136
#define PB 136

__device__ __forceinline__ void gemm_body(
    const float* __restrict__ A, const float* __restrict__ B,
    float* __restrict__ C, int M, int K, int N,
    const float* __restrict__ bias,
    unsigned* As, unsigned* Bs)
{
    const int t    = threadIdx.x;
    const int m0   = blockIdx.y * 128;
    const int n0   = blockIdx.x * 128;
    const int lane = t & 31;
    const int wid  = t >> 5;
    const int wm   = (wid >> 2) * 64;
    const int wn   = (wid & 3) * 32;
    const int gid  = lane >> 2;
    const int tg   = lane & 3;

    float acc[4][4][4];
#pragma unroll
    for (int i = 0; i < 4; i++)
#pragma unroll
        for (int j = 0; j < 4; j++)
#pragma unroll
            for (int r = 0; r < 4; r++) acc[i][j][r] = 0.f;

    for (int kt = 0; kt < K; kt += 16) {
#pragma unroll
        for (int i = 0; i < 2; i++) {
            int f  = t + i * 256;
            int m  = f >> 2;
            int kq = (f & 3) << 2;
            float4 val = make_float4(0.f, 0.f, 0.f, 0.f);
            int grow = m0 + m;
            if (grow < M)
                val = *(const float4*)(A + (size_t)grow * K + kt + kq);
            As[(kq + 0) * PA + m] = f2tf32(val.x);
            As[(kq + 1) * PA + m] = f2tf32(val.y);
            As[(kq + 2) * PA + m] = f2tf32(val.z);
            As[(kq + 3) * PA + m] = f2tf32(val.w);
        }
#pragma unroll
        for (int i = 0; i < 2; i++) {
            int f  = t + i * 256;
            int kr = f >> 5;
            int nq = (f & 31) << 2;
            float4 val = *(const float4*)(B + (size_t)(kt + kr) * N + n0 + nq);
            uint4 w;
            w.x = f2tf32(val.x); w.y = f2tf32(val.y);
            w.z = f2tf32(val.z); w.w = f2tf32(val.w);
            *(uint4*)(&Bs[kr * PB + nq]) = w;
        }
        __syncthreads();

#pragma unroll
        for (int kk = 0; kk < 16; kk += 8) {
            unsigned a[4][4], bf[4][2];
#pragma unroll
            for (int mf = 0; mf < 4; mf++) {
                int mb = wm + mf * 16 + gid;
                a[mf][0] = As[(kk + tg) * PA + mb];
                a[mf][1] = As[(kk + tg) * PA + mb + 8];
                a[mf][2] = As[(kk + tg + 4) * PA + mb];
                a[mf][3] = As[(kk + tg + 4) * PA + mb + 8];
            }
#pragma unroll
            for (int nf = 0; nf < 4; nf++) {
                int nb = wn + nf * 8 + gid;
                bf[nf][0] = Bs[(kk + tg) * PB + nb];
                bf[nf][1] = Bs[(kk + tg + 4) * PB + nb];
            }
#pragma unroll
            for (int mf = 0; mf < 4; mf++)
#pragma unroll
                for (int nf = 0; nf < 4; nf++)
                    asm volatile(
                        "mma.sync.aligned.m16n8k8.row.col.f32.tf32.tf32.f32 "
                        "{%0,%1,%2,%3}, {%4,%5,%6,%7}, {%8,%9}, {%0,%1,%2,%3};"
                        : "+f"(acc[mf][nf][0]), "+f"(acc[mf][nf][1]),
                          "+f"(acc[mf][nf][2]), "+f"(acc[mf][nf][3])
                        : "r"(a[mf][0]), "r"(a[mf][1]),
                          "r"(a[mf][2]), "r"(a[mf][3]),
                          "r"(bf[nf][0]), "r"(bf[nf][1]));
        }
        __syncthreads();
    }

#pragma unroll
    for (int mf = 0; mf < 4; mf++) {
#pragma unroll
        for (int nf = 0; nf < 4; nf++) {
            int row = m0 + wm + mf * 16 + gid;
            int col = n0 + wn + nf * 8 + tg * 2;
            float b0 = 0.f, b1 = 0.f;
            if (bias) { b0 = bias[col]; b1 = bias[col + 1]; }
            if (row < M) {
                float2 r0 = make_float2(acc[mf][nf][0] + b0, acc[mf][nf][1] + b1);
                *(float2*)(C + (size_t)row * N + col) = r0;
            }
            if (row + 8 < M) {
                float2 r1 = make_float2(acc[mf][nf][2] + b0, acc[mf][nf][3] + b1);
                *(float2*)(C + (size_t)(row + 8) * N + col) = r1;
            }
        }
    }
}

__global__ void __launch_bounds__(256, 2) gemm_tf32(
    const float* __restrict__ A, const float* __restrict__ B,
    float* __restrict__ C, int M, int K, int N,
    const float* __restrict__ bias)
{
    __shared__ unsigned As[16 * PA];
    __shared__ unsigned Bs[16 * PB];
    gemm_body(A, B, C, M, K, N, bias, As, Bs);
}

// K and V projections share A; one launch, blockIdx.z picks weight/output.
__global__ void __launch_bounds__(256, 2) gemm_tf32_dual(
    const float* __restrict__ A,
    const float* __restrict__ B0, float* __restrict__ C0,
    const float* __restrict__ B1, float* __restrict__ C1,
    int M, int K, int N)
{
    __shared__ unsigned As[16 * PA];
    __shared__ unsigned Bs[16 * PB];
    const float* B = blockIdx.z ? B1 : B0;
    float*       C = blockIdx.z ? C1 : C0;
    gemm_body(A, B, C, M, K, N, nullptr, As, Bs);
}

// ============================================================
// Fused cross-attention v2: 2 threads per query row.
// Each thread owns 32 of 64 dims; dot = 4 independent partial
// sums (chain length 8) + shfl.xor(1) combine. Upper-half threads
// iterate chunks XOR-4-rotated so the warp's two smem addresses
// per access differ by 64B mod 128B -> conflict-free.
// ============================================================
#define TILE_S 256
#define ATHR   512
#define KV_F4  (LTOK * (DHEAD / 4))          // 1232 float4
#define ATTN_SMEM ((2 * LTOK * DHEAD + TILE_S * DHEAD) * (int)sizeof(float))

__global__ void __launch_bounds__(ATHR) attn_kernel(
    const float* __restrict__ q, const float* __restrict__ k,
    const float* __restrict__ v, float* __restrict__ o)
{
    extern __shared__ float sm[];
    float* Ks = sm;                        // 77*64
    float* Vs = Ks + LTOK * DHEAD;         // 77*64
    float* Qs = Vs + LTOK * DHEAD;         // 256*64, xor-swizzled float4

    const int bh = blockIdx.y;
    const int b  = bh >> 4;
    const int h  = bh & 15;
    const int s0 = blockIdx.x * TILE_S;
    const int t  = threadIdx.x;

    // stage K, V (coalesced)
    const float* kbase = k + (size_t)(b * LTOK) * CDIM + h * DHEAD;
    const float* vbase = v + (size_t)(b * LTOK) * CDIM + h * DHEAD;
    for (int i = t; i < KV_F4; i += ATHR) {
        int j = i >> 4, c = i & 15;
        ((float4*)Ks)[j * 16 + c] = *(const float4*)(kbase + (size_t)j * CDIM + c * 4);
        ((float4*)Vs)[j * 16 + c] = *(const float4*)(vbase + (size_t)j * CDIM + c * 4);
    }
    // stage Q (coalesced), row-swizzled
    const float* qbase = q + (size_t)(b * SEQ + s0) * CDIM + h * DHEAD;
    for (int f = t; f < TILE_S * 16; f += ATHR) {
        int r = f >> 4, c = f & 15;
        float4 val = *(const float4*)(qbase + (size_t)r * CDIM + c * 4);
        ((float4*)Qs)[r * 16 + (c ^ (r & 7))] = val;
    }
    __syncthreads();

    const int row  = t >> 1;
    const int half = t & 1;
    const int sw   = row & 7;
    const int rot  = half ? 4 : 0;
    const int cbase = half ? 8 : 0;

    // chunk list this thread touches (within the 16-chunk head row)
    int ch[8];
#pragma unroll
    for (int c = 0; c < 8; c++) ch[c] = cbase + (c ^ rot);

    // Q half-row to registers
    float4 qr[8];
#pragma unroll
    for (int c = 0; c < 8; c++)
        qr[c] = ((const float4*)Qs)[row * 16 + (ch[c] ^ sw)];

    float accum[32];
#pragma unroll
    for (int d = 0; d < 32; d++) accum[d] = 0.f;
    float lsum = 0.f;
    const float scale = 0.125f;  // 1/sqrt(64)

    for (int j = 0; j < LTOK; j++) {
        float p0 = 0.f, p1 = 0.f, p2 = 0.f, p3 = 0.f;
#pragma unroll
        for (int c = 0; c < 8; c++) {
            float4 kv = ((const float4*)Ks)[j * 16 + ch[c]];
            p0 += qr[c].x * kv.x;
            p1 += qr[c].y * kv.y;
            p2 += qr[c].z * kv.z;
            p3 += qr[c].w * kv.w;
        }
        float s = (p0 + p1) + (p2 + p3);
        s += __shfl_xor_sync(0xffffffffu, s, 1);
        float e = __expf(s * scale);
        lsum += e;
#pragma unroll
        for (int c = 0; c < 8; c++) {
            float4 vv = ((const float4*)Vs)[j * 16 + ch[c]];
            accum[c * 4 + 0] += e * vv.x;
            accum[c * 4 + 1] += e * vv.y;
            accum[c * 4 + 2] += e * vv.z;
            accum[c * 4 + 3] += e * vv.w;
        }
    }

    const float inv = 1.0f / lsum;
    float* obase = o + (size_t)(b * SEQ + s0 + row) * CDIM + h * DHEAD;
#pragma unroll
    for (int c = 0; c < 8; c++) {
        float4 r = make_float4(accum[c * 4 + 0] * inv, accum[c * 4 + 1] * inv,
                               accum[c * 4 + 2] * inv, accum[c * 4 + 3] * inv);
        ((float4*)obase)[ch[c]] = r;
    }
}

// ============================================================
// launch
// ============================================================
extern "C" void kernel_launch(void* const* d_in, const int* in_sizes, int n_in,
                              void* d_out, int out_size)
{
    const float* hs  = (const float*)d_in[0];
    const float* enc = (const float*)d_in[1];
    const float* Wq  = (const float*)d_in[2];
    const float* Wk  = (const float*)d_in[3];
    const float* Wv  = (const float*)d_in[4];
    const float* Wo  = (const float*)d_in[5];
    const float* bo  = (const float*)d_in[6];
    float* out = (float*)d_out;
    (void)in_sizes; (void)n_in; (void)out_size;

    float *qb, *kb, *vb, *ab;
    cudaGetSymbolAddress((void**)&qb, g_q);
    cudaGetSymbolAddress((void**)&kb, g_k);
    cudaGetSymbolAddress((void**)&vb, g_v);
    cudaGetSymbolAddress((void**)&ab, g_attn);

    dim3 blk(256);

    // q = hs @ Wq
    gemm_tf32<<<dim3(CDIM / 128, MQ / 128), blk>>>(hs, Wq, qb, MQ, CDIM, CDIM, nullptr);
    // k,v = enc @ {Wk,Wv} fused into one launch
    gemm_tf32_dual<<<dim3(CDIM / 128, (MKV + 127) / 128, 2), blk>>>(
        enc, Wk, kb, Wv, vb, MKV, CENC, CDIM);

    // fused attention (pair-split rows)
    cudaFuncSetAttribute(attn_kernel, cudaFuncAttributeMaxDynamicSharedMemorySize, ATTN_SMEM);
    attn_kernel<<<dim3(SEQ / TILE_S, BATCH * NHEAD), ATHR, ATTN_SMEM>>>(qb, kb, vb, ab);

    // out = attn @ Wo + bo
    gemm_tf32<<<dim3(CDIM / 128, MQ / 128), blk>>>(ab, Wo, out, MQ, CDIM, CDIM, bo);
}

// round 6
// speedup vs baseline: 1.2507x; 1.1786x over previous
#include <cuda_runtime.h>
#include <cstdint>

// ---------------- problem constants ----------------
#define BATCH   16
#define SEQ     4096
#define CDIM    1024
#define NHEAD   16
#define DHEAD   64
#define LTOK    77
#define CENC    768
#define MQ      (BATCH*SEQ)      // 65536
#define MKV     (BATCH*LTOK)     // 1232

// ---------------- scratch ----------------
__device__ float g_q[(size_t)MQ * CDIM];
__device__ float g_attn[(size_t)MQ * CDIM];
__device__ float g_hs[(size_t)MQ * CDIM];
__device__ float g_k[(size_t)MKV * CDIM];
__device__ float g_v[(size_t)MKV * CDIM];
__device__ float g_wq[CDIM * CDIM];
__device__ float g_wo[CDIM * CDIM];

__device__ __forceinline__ unsigned f2tf32(float x) {
    unsigned r;
    asm("cvt.rna.tf32.f32 %0, %1;" : "=r"(r) : "f"(x));
    return r;
}
__device__ __forceinline__ float rnd_tf32(float x) { return __uint_as_float(f2tf32(x)); }

__device__ __forceinline__ uint32_t smem_u32(const void* p) {
    uint32_t a;
    asm("{ .reg .u64 t; cvta.to.shared.u64 t, %1; cvt.u32.u64 %0, t; }" : "=r"(a) : "l"(p));
    return a;
}
#define CP16(dst, src) \
    asm volatile("cp.async.cg.shared.global [%0], [%1], 16;" :: "r"(dst), "l"(src) : "memory")
#define CP_COMMIT() asm volatile("cp.async.commit_group;" ::: "memory")
#define CP_WAIT2()  asm volatile("cp.async.wait_group 2;" ::: "memory")

// ============================================================
// Pipelined TF32 GEMM for pre-rounded operands.
// C[M,N] = A[M,K] @ B[K,N] (+bias). M%128==0, N%128==0, K%16==0.
// 4-stage cp.async pipeline, K-chunk 16, block 128x128, 256 thr.
// A smem row stride 20 floats (conflict-free frag loads), B stride 136.
// ============================================================
#define NSTAGE  4
#define KC      16
#define PA2     20
#define PB2     136
#define A_BYTES (128 * PA2 * 4)              // 10240
#define B_BYTES (KC * PB2 * 4)               // 8704
#define STG_B   (A_BYTES + B_BYTES)          // 18944
#define PIPE_SMEM (NSTAGE * STG_B)           // 75776

__device__ __forceinline__ void pipe_issue(
    uint32_t sb, int s, const float* __restrict__ A, const float* __restrict__ B,
    int m0, int n0, int kt, int K, int N, int t)
{
    uint32_t base = sb + s * STG_B;
#pragma unroll
    for (int i = 0; i < 2; i++) {
        int f = t + i * 256;
        int m = f >> 2, c = f & 3;
        CP16(base + m * (PA2 * 4) + c * 16,
             A + (size_t)(m0 + m) * K + kt + c * 4);
    }
#pragma unroll
    for (int i = 0; i < 2; i++) {
        int f = t + i * 256;
        int kr = f >> 5, nq = (f & 31) << 2;
        CP16(base + A_BYTES + kr * (PB2 * 4) + nq * 4,
             B + (size_t)(kt + kr) * N + n0 + nq);
    }
    CP_COMMIT();
}

__global__ void __launch_bounds__(256, 2) gemm_pipe(
    const float* __restrict__ A, const float* __restrict__ B,
    float* __restrict__ C, int M, int K, int N,
    const float* __restrict__ bias)
{
    extern __shared__ char smem[];
    const uint32_t sb = smem_u32(smem);

    const int t    = threadIdx.x;
    const int m0   = blockIdx.y * 128;
    const int n0   = blockIdx.x * 128;
    const int lane = t & 31;
    const int wid  = t >> 5;
    const int wm   = (wid >> 2) * 64;
    const int wn   = (wid & 3) * 32;
    const int gid  = lane >> 2;
    const int tg   = lane & 3;
    const int nk   = K / KC;

    float acc[4][4][4];
#pragma unroll
    for (int i = 0; i < 4; i++)
#pragma unroll
        for (int j = 0; j < 4; j++)
#pragma unroll
            for (int r = 0; r < 4; r++) acc[i][j][r] = 0.f;

    // prologue: stages 0..2
#pragma unroll
    for (int s = 0; s < NSTAGE - 1; s++)
        pipe_issue(sb, s, A, B, m0, n0, s * KC, K, N, t);

    for (int ki = 0; ki < nk; ki++) {
        const int s = ki & (NSTAGE - 1);
        CP_WAIT2();
        __syncthreads();

        // prefetch stage ki+3 (overwrites buffer of ki-1, freed by the sync)
        if (ki + NSTAGE - 1 < nk)
            pipe_issue(sb, (ki + NSTAGE - 1) & (NSTAGE - 1), A, B, m0, n0,
                       (ki + NSTAGE - 1) * KC, K, N, t);
        else
            CP_COMMIT();  // keep group count uniform

        const unsigned* As = (const unsigned*)(smem + (size_t)s * STG_B);
        const unsigned* Bs = (const unsigned*)(smem + (size_t)s * STG_B + A_BYTES);

#pragma unroll
        for (int kk = 0; kk < KC; kk += 8) {
            unsigned a[4][4], bf[4][2];
#pragma unroll
            for (int mf = 0; mf < 4; mf++) {
                int mb = wm + mf * 16 + gid;
                a[mf][0] = As[mb * PA2 + kk + tg];
                a[mf][1] = As[(mb + 8) * PA2 + kk + tg];
                a[mf][2] = As[mb * PA2 + kk + tg + 4];
                a[mf][3] = As[(mb + 8) * PA2 + kk + tg + 4];
            }
#pragma unroll
            for (int nf = 0; nf < 4; nf++) {
                int nb = wn + nf * 8 + gid;
                bf[nf][0] = Bs[(kk + tg) * PB2 + nb];
                bf[nf][1] = Bs[(kk + tg + 4) * PB2 + nb];
            }
#pragma unroll
            for (int mf = 0; mf < 4; mf++)
#pragma unroll
                for (int nf = 0; nf < 4; nf++)
                    asm volatile(
                        "mma.sync.aligned.m16n8k8.row.col.f32.tf32.tf32.f32 "
                        "{%0,%1,%2,%3}, {%4,%5,%6,%7}, {%8,%9}, {%0,%1,%2,%3};"
                        : "+f"(acc[mf][nf][0]), "+f"(acc[mf][nf][1]),
                          "+f"(acc[mf][nf][2]), "+f"(acc[mf][nf][3])
                        : "r"(a[mf][0]), "r"(a[mf][1]),
                          "r"(a[mf][2]), "r"(a[mf][3]),
                          "r"(bf[nf][0]), "r"(bf[nf][1]));
        }
    }

#pragma unroll
    for (int mf = 0; mf < 4; mf++) {
#pragma unroll
        for (int nf = 0; nf < 4; nf++) {
            int row = m0 + wm + mf * 16 + gid;
            int col = n0 + wn + nf * 8 + tg * 2;
            float b0 = 0.f, b1 = 0.f;
            if (bias) { b0 = bias[col]; b1 = bias[col + 1]; }
            *(float2*)(C + (size_t)row * N + col) =
                make_float2(acc[mf][nf][0] + b0, acc[mf][nf][1] + b1);
            *(float2*)(C + (size_t)(row + 8) * N + col) =
                make_float2(acc[mf][nf][2] + b0, acc[mf][nf][3] + b1);
        }
    }
}

// ---------------- tf32 pre-round pass ----------------
__global__ void cvt_tf32_kernel(const float4* __restrict__ in, float4* __restrict__ out, int n4) {
    int i = blockIdx.x * blockDim.x + threadIdx.x;
    if (i < n4) {
        float4 v = in[i];
        v.x = rnd_tf32(v.x); v.y = rnd_tf32(v.y);
        v.z = rnd_tf32(v.z); v.w = rnd_tf32(v.w);
        out[i] = v;
    }
}

// ============================================================
// Legacy single-buffer GEMM (only for the small ragged K/V projections)
// ============================================================
#define PA 136
#define PB 136

__device__ __forceinline__ void gemm_body(
    const float* __restrict__ A, const float* __restrict__ B,
    float* __restrict__ C, int M, int K, int N,
    unsigned* As, unsigned* Bs)
{
    const int t    = threadIdx.x;
    const int m0   = blockIdx.y * 128;
    const int n0   = blockIdx.x * 128;
    const int lane = t & 31;
    const int wid  = t >> 5;
    const int wm   = (wid >> 2) * 64;
    const int wn   = (wid & 3) * 32;
    const int gid  = lane >> 2;
    const int tg   = lane & 3;

    float acc[4][4][4];
#pragma unroll
    for (int i = 0; i < 4; i++)
#pragma unroll
        for (int j = 0; j < 4; j++)
#pragma unroll
            for (int r = 0; r < 4; r++) acc[i][j][r] = 0.f;

    for (int kt = 0; kt < K; kt += 16) {
#pragma unroll
        for (int i = 0; i < 2; i++) {
            int f  = t + i * 256;
            int m  = f >> 2;
            int kq = (f & 3) << 2;
            float4 val = make_float4(0.f, 0.f, 0.f, 0.f);
            if (m0 + m < M)
                val = *(const float4*)(A + (size_t)(m0 + m) * K + kt + kq);
            As[(kq + 0) * PA + m] = f2tf32(val.x);
            As[(kq + 1) * PA + m] = f2tf32(val.y);
            As[(kq + 2) * PA + m] = f2tf32(val.z);
            As[(kq + 3) * PA + m] = f2tf32(val.w);
        }
#pragma unroll
        for (int i = 0; i < 2; i++) {
            int f  = t + i * 256;
            int kr = f >> 5;
            int nq = (f & 31) << 2;
            float4 val = *(const float4*)(B + (size_t)(kt + kr) * N + n0 + nq);
            uint4 w;
            w.x = f2tf32(val.x); w.y = f2tf32(val.y);
            w.z = f2tf32(val.z); w.w = f2tf32(val.w);
            *(uint4*)(&Bs[kr * PB + nq]) = w;
        }
        __syncthreads();

#pragma unroll
        for (int kk = 0; kk < 16; kk += 8) {
            unsigned a[4][4], bf[4][2];
#pragma unroll
            for (int mf = 0; mf < 4; mf++) {
                int mb = wm + mf * 16 + gid;
                a[mf][0] = As[(kk + tg) * PA + mb];
                a[mf][1] = As[(kk + tg) * PA + mb + 8];
                a[mf][2] = As[(kk + tg + 4) * PA + mb];
                a[mf][3] = As[(kk + tg + 4) * PA + mb + 8];
            }
#pragma unroll
            for (int nf = 0; nf < 4; nf++) {
                int nb = wn + nf * 8 + gid;
                bf[nf][0] = Bs[(kk + tg) * PB + nb];
                bf[nf][1] = Bs[(kk + tg + 4) * PB + nb];
            }
#pragma unroll
            for (int mf = 0; mf < 4; mf++)
#pragma unroll
                for (int nf = 0; nf < 4; nf++)
                    asm volatile(
                        "mma.sync.aligned.m16n8k8.row.col.f32.tf32.tf32.f32 "
                        "{%0,%1,%2,%3}, {%4,%5,%6,%7}, {%8,%9}, {%0,%1,%2,%3};"
                        : "+f"(acc[mf][nf][0]), "+f"(acc[mf][nf][1]),
                          "+f"(acc[mf][nf][2]), "+f"(acc[mf][nf][3])
                        : "r"(a[mf][0]), "r"(a[mf][1]),
                          "r"(a[mf][2]), "r"(a[mf][3]),
                          "r"(bf[nf][0]), "r"(bf[nf][1]));
        }
        __syncthreads();
    }

#pragma unroll
    for (int mf = 0; mf < 4; mf++) {
#pragma unroll
        for (int nf = 0; nf < 4; nf++) {
            int row = m0 + wm + mf * 16 + gid;
            int col = n0 + wn + nf * 8 + tg * 2;
            if (row < M)
                *(float2*)(C + (size_t)row * N + col) =
                    make_float2(acc[mf][nf][0], acc[mf][nf][1]);
            if (row + 8 < M)
                *(float2*)(C + (size_t)(row + 8) * N + col) =
                    make_float2(acc[mf][nf][2], acc[mf][nf][3]);
        }
    }
}

__global__ void __launch_bounds__(256, 2) gemm_tf32_dual(
    const float* __restrict__ A,
    const float* __restrict__ B0, float* __restrict__ C0,
    const float* __restrict__ B1, float* __restrict__ C1,
    int M, int K, int N)
{
    __shared__ unsigned As[16 * PA];
    __shared__ unsigned Bs[16 * PB];
    const float* B = blockIdx.z ? B1 : B0;
    float*       C = blockIdx.z ? C1 : C0;
    gemm_body(A, B, C, M, K, N, As, Bs);
}

// ============================================================
// Fused cross-attention (R5 pair-split variant) — output now
// tf32-rna-rounded so the Wo pipeline GEMM consumes it directly.
// ============================================================
#define TILE_S 256
#define ATHR   512
#define KV_F4  (LTOK * (DHEAD / 4))
#define ATTN_SMEM ((2 * LTOK * DHEAD + TILE_S * DHEAD) * (int)sizeof(float))

__global__ void __launch_bounds__(ATHR) attn_kernel(
    const float* __restrict__ q, const float* __restrict__ k,
    const float* __restrict__ v, float* __restrict__ o)
{
    extern __shared__ float sm[];
    float* Ks = sm;
    float* Vs = Ks + LTOK * DHEAD;
    float* Qs = Vs + LTOK * DHEAD;

    const int bh = blockIdx.y;
    const int b  = bh >> 4;
    const int h  = bh & 15;
    const int s0 = blockIdx.x * TILE_S;
    const int t  = threadIdx.x;

    const float* kbase = k + (size_t)(b * LTOK) * CDIM + h * DHEAD;
    const float* vbase = v + (size_t)(b * LTOK) * CDIM + h * DHEAD;
    for (int i = t; i < KV_F4; i += ATHR) {
        int j = i >> 4, c = i & 15;
        ((float4*)Ks)[j * 16 + c] = *(const float4*)(kbase + (size_t)j * CDIM + c * 4);
        ((float4*)Vs)[j * 16 + c] = *(const float4*)(vbase + (size_t)j * CDIM + c * 4);
    }
    const float* qbase = q + (size_t)(b * SEQ + s0) * CDIM + h * DHEAD;
    for (int f = t; f < TILE_S * 16; f += ATHR) {
        int r = f >> 4, c = f & 15;
        float4 val = *(const float4*)(qbase + (size_t)r * CDIM + c * 4);
        ((float4*)Qs)[r * 16 + (c ^ (r & 7))] = val;
    }
    __syncthreads();

    const int row   = t >> 1;
    const int half  = t & 1;
    const int sw    = row & 7;
    const int rot   = half ? 4 : 0;
    const int cbase = half ? 8 : 0;

    int ch[8];
#pragma unroll
    for (int c = 0; c < 8; c++) ch[c] = cbase + (c ^ rot);

    float4 qr[8];
#pragma unroll
    for (int c = 0; c < 8; c++)
        qr[c] = ((const float4*)Qs)[row * 16 + (ch[c] ^ sw)];

    float accum[32];
#pragma unroll
    for (int d = 0; d < 32; d++) accum[d] = 0.f;
    float lsum = 0.f;
    const float scale = 0.125f;

    for (int j = 0; j < LTOK; j++) {
        float p0 = 0.f, p1 = 0.f, p2 = 0.f, p3 = 0.f;
#pragma unroll
        for (int c = 0; c < 8; c++) {
            float4 kv = ((const float4*)Ks)[j * 16 + ch[c]];
            p0 += qr[c].x * kv.x;
            p1 += qr[c].y * kv.y;
            p2 += qr[c].z * kv.z;
            p3 += qr[c].w * kv.w;
        }
        float s = (p0 + p1) + (p2 + p3);
        s += __shfl_xor_sync(0xffffffffu, s, 1);
        float e = __expf(s * scale);
        lsum += e;
#pragma unroll
        for (int c = 0; c < 8; c++) {
            float4 vv = ((const float4*)Vs)[j * 16 + ch[c]];
            accum[c * 4 + 0] += e * vv.x;
            accum[c * 4 + 1] += e * vv.y;
            accum[c * 4 + 2] += e * vv.z;
            accum[c * 4 + 3] += e * vv.w;
        }
    }

    const float inv = 1.0f / lsum;
    float* obase = o + (size_t)(b * SEQ + s0 + row) * CDIM + h * DHEAD;
#pragma unroll
    for (int c = 0; c < 8; c++) {
        float4 r;
        r.x = rnd_tf32(accum[c * 4 + 0] * inv);
        r.y = rnd_tf32(accum[c * 4 + 1] * inv);
        r.z = rnd_tf32(accum[c * 4 + 2] * inv);
        r.w = rnd_tf32(accum[c * 4 + 3] * inv);
        ((float4*)obase)[ch[c]] = r;
    }
}

// ============================================================
// launch
// ============================================================
extern "C" void kernel_launch(void* const* d_in, const int* in_sizes, int n_in,
                              void* d_out, int out_size)
{
    const float* hs  = (const float*)d_in[0];
    const float* enc = (const float*)d_in[1];
    const float* Wq  = (const float*)d_in[2];
    const float* Wk  = (const float*)d_in[3];
    const float* Wv  = (const float*)d_in[4];
    const float* Wo  = (const float*)d_in[5];
    const float* bo  = (const float*)d_in[6];
    float* out = (float*)d_out;
    (void)in_sizes; (void)n_in; (void)out_size;

    float *qb, *kb, *vb, *ab, *hsb, *wqb, *wob;
    cudaGetSymbolAddress((void**)&qb,  g_q);
    cudaGetSymbolAddress((void**)&kb,  g_k);
    cudaGetSymbolAddress((void**)&vb,  g_v);
    cudaGetSymbolAddress((void**)&ab,  g_attn);
    cudaGetSymbolAddress((void**)&hsb, g_hs);
    cudaGetSymbolAddress((void**)&wqb, g_wq);
    cudaGetSymbolAddress((void**)&wob, g_wo);

    // pre-round pipeline-GEMM operands to tf32 (rna)
    cvt_tf32_kernel<<<(MQ * CDIM / 4 + 255) / 256, 256>>>((const float4*)hs, (float4*)hsb, MQ * CDIM / 4);
    cvt_tf32_kernel<<<(CDIM * CDIM / 4 + 255) / 256, 256>>>((const float4*)Wq, (float4*)wqb, CDIM * CDIM / 4);
    cvt_tf32_kernel<<<(CDIM * CDIM / 4 + 255) / 256, 256>>>((const float4*)Wo, (float4*)wob, CDIM * CDIM / 4);

    cudaFuncSetAttribute(gemm_pipe, cudaFuncAttributeMaxDynamicSharedMemorySize, PIPE_SMEM);

    // q = hs @ Wq  (pipelined)
    gemm_pipe<<<dim3(CDIM / 128, MQ / 128), 256, PIPE_SMEM>>>(hsb, wqb, qb, MQ, CDIM, CDIM, nullptr);

    // k,v = enc @ {Wk,Wv}  (legacy, ragged M)
    gemm_tf32_dual<<<dim3(CDIM / 128, (MKV + 127) / 128, 2), 256>>>(
        enc, Wk, kb, Wv, vb, MKV, CENC, CDIM);

    // fused attention (writes tf32-rounded output)
    cudaFuncSetAttribute(attn_kernel, cudaFuncAttributeMaxDynamicSharedMemorySize, ATTN_SMEM);
    attn_kernel<<<dim3(SEQ / TILE_S, BATCH * NHEAD), ATHR, ATTN_SMEM>>>(qb, kb, vb, ab);

    // out = attn @ Wo + bo  (pipelined)
    gemm_pipe<<<dim3(CDIM / 128, MQ / 128), 256, PIPE_SMEM>>>(ab, wob, out, MQ, CDIM, CDIM, bo);
}